// round 9
// baseline (speedup 1.0000x reference)
#include <cuda_runtime.h>
#include <cuda_fp16.h>
#include <cstdint>

#define BB 2
#define SS 2048
#define EE 1024
#define HH 16
#define DD 64
#define MM (BB*SS)
#define SCALE 0.125f
#define LOG2E 1.44269504f
#define GK 1024
#define GN 1024

// ---------------- scratch ----------------
__device__ __half g_Xh[MM*EE];
__device__ __half g_WT[5][EE*EE];   // 0=q 1=k 2=v 3=g 4=o, [n][k]
__device__ __half g_Qh[MM*EE];
__device__ __half g_Kh[MM*EE];
__device__ __half g_Vt[MM*EE];      // [b][h][d][tok]
__device__ __half g_Gh[MM*EE];      // sigmoid(gate), half
__device__ __half g_O0h[MM*EE];
__device__ __half g_O1h[MM*EE];
__device__ __half g_Oh[MM*EE];

// ---------------- helpers ----------------
__device__ __forceinline__ uint32_t smem_u32(const void* p) {
    return (uint32_t)__cvta_generic_to_shared(p);
}
#define CP16(d_, s_) asm volatile("cp.async.cg.shared.global [%0],[%1],16;\n" :: "r"(d_), "l"(s_))
#define CPCOMMIT() asm volatile("cp.async.commit_group;\n")
#define CPWAIT1() asm volatile("cp.async.wait_group 1;\n")
#define CPWAIT0() asm volatile("cp.async.wait_group 0;\n")
#define LDM4(R0,R1,R2,R3,ADDR) \
    asm volatile("ldmatrix.sync.aligned.m8n8.x4.shared.b16 {%0,%1,%2,%3}, [%4];" \
        : "=r"(R0), "=r"(R1), "=r"(R2), "=r"(R3) : "r"(ADDR))

__device__ __forceinline__ void mma16(float* d, const uint32_t* a, const uint32_t* b) {
    asm volatile(
        "mma.sync.aligned.m16n8k16.row.col.f32.f16.f16.f32 "
        "{%0,%1,%2,%3}, {%4,%5,%6,%7}, {%8,%9}, {%0,%1,%2,%3};"
        : "+f"(d[0]), "+f"(d[1]), "+f"(d[2]), "+f"(d[3])
        : "r"(a[0]), "r"(a[1]), "r"(a[2]), "r"(a[3]), "r"(b[0]), "r"(b[1]));
}
__device__ __forceinline__ uint32_t h2u(float x, float y) {
    __half2 h = __floats2half2_rn(x, y);
    return *(uint32_t*)&h;
}
__device__ __forceinline__ float fex2(float x) {
    float y; asm("ex2.approx.f32 %0, %1;" : "=f"(y) : "f"(x)); return y;
}

// ---------------- prep ----------------
__global__ void prep_x(const float* __restrict__ x) {
    int i = blockIdx.x * 256 + threadIdx.x;
    float2 v = ((const float2*)x)[i];
    ((__half2*)g_Xh)[i] = __floats2half2_rn(v.x, v.y);
}
__global__ void prep_w(const float* Wq, const float* Wk, const float* Wv,
                       const float* Wg, const float* Wo) {
    __shared__ float t[32][33];
    int z = blockIdx.z;
    const float* W = z==0?Wq : z==1?Wk : z==2?Wv : z==3?Wg : Wo;
    __half* D = g_WT[z];
    int n0 = blockIdx.x*32, k0 = blockIdx.y*32;
    int tx = threadIdx.x, ty = threadIdx.y;
#pragma unroll
    for (int j = 0; j < 4; ++j)
        t[ty + j*8][tx] = W[(size_t)(k0 + ty + j*8)*GN + n0 + tx];
    __syncthreads();
#pragma unroll
    for (int j = 0; j < 4; ++j)
        D[(size_t)(n0 + ty + j*8)*GK + k0 + tx] = __float2half_rn(t[tx][ty + j*8]);
}
__global__ void sum_o() {
    int i = blockIdx.x * 256 + threadIdx.x;
    ((__half2*)g_Oh)[i] = __hadd2(((const __half2*)g_O0h)[i], ((const __half2*)g_O1h)[i]);
}

// ---------------- GEMM core ----------------
#define AST 72
#define TILE_H (128*AST)
#define GEMM_SMEM (4*TILE_H*2)

__device__ __forceinline__ void gemm_core(
    const __half* __restrict__ A, const __half* __restrict__ Bt,
    const float* __restrict__ bias, float* __restrict__ fC,
    __half* __restrict__ hC, int mode)
{
    extern __shared__ char smp[];
    __half* As = (__half*)smp;
    __half* Bs = (__half*)smp + 2*TILE_H;

    const int tid = threadIdx.x, lane = tid & 31, wid = tid >> 5;
    const int wm = wid >> 1, wn = wid & 1, g = lane >> 2, c = lane & 3;
    const int row0 = blockIdx.y*128, col0 = blockIdx.x*128;
    const int LOFF = ((lane & 15)*AST + ((lane >> 4) << 3)) * 2;  // bytes

    float acc[4][8][4];
#pragma unroll
    for (int mi = 0; mi < 4; ++mi)
#pragma unroll
        for (int ni = 0; ni < 8; ++ni) {
            acc[mi][ni][0]=0.f; acc[mi][ni][1]=0.f; acc[mi][ni][2]=0.f; acc[mi][ni][3]=0.f;
        }

    {
#pragma unroll
        for (int u = 0; u < 8; ++u) {
            int idx = tid + u*128, m = idx >> 3, ko = (idx & 7)*8;
            CP16(smem_u32(&As[m*AST + ko]), &A[(size_t)(row0+m)*GK + ko]);
            CP16(smem_u32(&Bs[m*AST + ko]), &Bt[(size_t)(col0+m)*GK + ko]);
        }
        CPCOMMIT();
    }

#pragma unroll 1
    for (int it = 0; it < 16; ++it) {
        if (it < 15) {
            int buf = (it+1) & 1, k0 = (it+1)*64;
#pragma unroll
            for (int u = 0; u < 8; ++u) {
                int idx = tid + u*128, m = idx >> 3, ko = (idx & 7)*8;
                CP16(smem_u32(&As[buf*TILE_H + m*AST + ko]), &A[(size_t)(row0+m)*GK + k0 + ko]);
                CP16(smem_u32(&Bs[buf*TILE_H + m*AST + ko]), &Bt[(size_t)(col0+m)*GK + k0 + ko]);
            }
            CPCOMMIT();
            CPWAIT1();
        } else {
            CPWAIT0();
        }
        __syncthreads();
        const uint32_t abase = smem_u32(&As[(it & 1)*TILE_H]) + wm*64*AST*2 + LOFF;
        const uint32_t bbase = smem_u32(&Bs[(it & 1)*TILE_H]) + wn*64*AST*2 + LOFF;
#pragma unroll
        for (int ks = 0; ks < 4; ++ks) {
            const int kb2 = ks*32;  // 16 halves in bytes
            uint32_t a[4][4], bf[4][4];
#pragma unroll
            for (int mi = 0; mi < 4; ++mi)
                LDM4(a[mi][0], a[mi][1], a[mi][2], a[mi][3], abase + mi*16*AST*2 + kb2);
#pragma unroll
            for (int j = 0; j < 4; ++j)
                LDM4(bf[j][0], bf[j][1], bf[j][2], bf[j][3], bbase + j*16*AST*2 + kb2);
#pragma unroll
            for (int j = 0; j < 4; ++j) {
                uint32_t be[2] = {bf[j][0], bf[j][2]};
                uint32_t bo[2] = {bf[j][1], bf[j][3]};
#pragma unroll
                for (int mi = 0; mi < 4; ++mi) {
                    mma16(acc[mi][2*j],   a[mi], be);
                    mma16(acc[mi][2*j+1], a[mi], bo);
                }
            }
        }
        __syncthreads();
    }

#pragma unroll
    for (int mi = 0; mi < 4; ++mi) {
#pragma unroll
        for (int ni = 0; ni < 8; ++ni) {
            int r = row0 + wm*64 + mi*16 + g;
            int col = col0 + wn*64 + ni*8 + 2*c;
            float b0 = 0.f, b1 = 0.f;
            if (bias) { b0 = bias[col]; b1 = bias[col+1]; }
            float v0 = acc[mi][ni][0]+b0, v1 = acc[mi][ni][1]+b1;
            float v2 = acc[mi][ni][2]+b0, v3 = acc[mi][ni][3]+b1;
            if (mode == 0) {
                const float f = SCALE * LOG2E;
                v0*=f; v1*=f; v2*=f; v3*=f;
            }
            if (mode == 4) {
                *(float2*)&fC[(size_t)r*GN + col] = make_float2(v0, v1);
                *(float2*)&fC[(size_t)(r+8)*GN + col] = make_float2(v2, v3);
            } else if (mode == 3) {
                float s0 = 1.f/(1.f+__expf(-v0)), s1 = 1.f/(1.f+__expf(-v1));
                float s2 = 1.f/(1.f+__expf(-v2)), s3 = 1.f/(1.f+__expf(-v3));
                *(__half2*)&hC[(size_t)r*GN + col] = __floats2half2_rn(s0, s1);
                *(__half2*)&hC[(size_t)(r+8)*GN + col] = __floats2half2_rn(s2, s3);
            } else if (mode == 2) {
                int bi = r >> 11, tok = r & 2047, hh = col >> 6, d = col & 63;
                __half* Vb = &g_Vt[(size_t)((bi*HH + hh)*DD) * SS];
                Vb[(size_t)d*SS + tok]       = __float2half_rn(v0);
                Vb[(size_t)(d+1)*SS + tok]   = __float2half_rn(v1);
                Vb[(size_t)d*SS + tok+8]     = __float2half_rn(v2);
                Vb[(size_t)(d+1)*SS + tok+8] = __float2half_rn(v3);
            } else {
                *(__half2*)&hC[(size_t)r*GN + col] = __floats2half2_rn(v0, v1);
                *(__half2*)&hC[(size_t)(r+8)*GN + col] = __floats2half2_rn(v2, v3);
            }
        }
    }
}

__global__ __launch_bounds__(128) void gemm_qkvg(
    const float* bq, const float* bk, const float* bv)
{
    int z = blockIdx.z;
    const float* bias = z==0?bq : z==1?bk : z==2?bv : nullptr;
    __half* hC = z==0?g_Qh : z==1?g_Kh : z==2?nullptr : g_Gh;
    gemm_core(g_Xh, g_WT[z], bias, nullptr, hC, z);
}
__global__ __launch_bounds__(128) void gemm_out(const float* bo, float* out)
{
    gemm_core(g_Oh, g_WT[4], bo, out, nullptr, 4);
}

// ---------------- Attention: mi=2 register-P flash + ldmatrix ----
#define KST 72
#define Q_OFF 0
#define K_OFF (128*KST)
#define V_OFF (K_OFF + 2*64*KST)
#define MSK_OFF_B ((V_OFF + 2*64*KST)*2)
#define ATT_SMEM (MSK_OFF_B + 128)

__global__ __launch_bounds__(128) void attn_h(const unsigned char* __restrict__ mask)
{
    extern __shared__ char smc[];
    __half* Qs = (__half*)smc + Q_OFF;
    __half* Ks = (__half*)smc + K_OFF;
    __half* Vs = (__half*)smc + V_OFF;
    unsigned char* mskb = (unsigned char*)smc + MSK_OFF_B;

    const int tid = threadIdx.x, lane = tid & 31, wid = tid >> 5;
    const int g = lane >> 2, c = lane & 3;
    const int h = blockIdx.y, z = blockIdx.z;
    const int b = z >> 1, p = z & 1;
    const int q0 = blockIdx.x*128, hoff = h*DD;
    const int kbase = p*1024;
    const float pw = p ? 1.0f : 0.5f;
    const int wrow = wid*32;
    const int LOFF = ((lane & 15)*KST + ((lane >> 4) << 3)) * 2;  // bytes
    const __half* Kg = &g_Kh[(size_t)b*SS*EE + hoff];
    const __half* Vg = &g_Vt[(size_t)(b*HH + h)*DD*SS];

    auto issue = [&](int t) {
        int buf = t & 1, k0g = kbase + t*64;
#pragma unroll
        for (int u = 0; u < 4; ++u) {
            int idx = tid + u*128, r = idx >> 3, ko = (idx & 7)*8;
            CP16(smem_u32(&Ks[buf*64*KST + r*KST + ko]), &Kg[(size_t)(k0g + r)*EE + ko]);
            CP16(smem_u32(&Vs[buf*64*KST + r*KST + ko]), &Vg[(size_t)r*SS + k0g + ko]);
        }
        if (tid < 4)
            CP16(smem_u32(&mskb[(t & 1)*64 + tid*16]), &mask[(size_t)b*SS + k0g + tid*16]);
        CPCOMMIT();
    };

#pragma unroll
    for (int u = 0; u < 8; ++u) {
        int idx = tid + u*128, r = idx >> 3, ko = (idx & 7)*8;
        CP16(smem_u32(&Qs[r*KST + ko]), &g_Qh[(size_t)(b*SS + q0 + r)*EE + hoff + ko]);
    }
    issue(0);

    const uint32_t qb0 = smem_u32(Qs) + wrow*KST*2 + LOFF;
    const uint32_t qb1 = qb0 + 16*KST*2;

    float o[2][8][4];
    float l[2][2] = {{0.f,0.f},{0.f,0.f}};
#pragma unroll
    for (int mi = 0; mi < 2; ++mi)
#pragma unroll
        for (int ni = 0; ni < 8; ++ni) {
            o[mi][ni][0]=0.f; o[mi][ni][1]=0.f; o[mi][ni][2]=0.f; o[mi][ni][3]=0.f;
        }

#pragma unroll 1
    for (int t = 0; t < 16; ++t) {
        if (t < 15) { issue(t + 1); CPWAIT1(); } else { CPWAIT0(); }
        __syncthreads();
        const uint32_t kpb = smem_u32(&Ks[(t & 1)*64*KST]) + LOFF;
        const uint32_t vpb = smem_u32(&Vs[(t & 1)*64*KST]) + LOFF;
        const unsigned char* mb = &mskb[(t & 1)*64];

        // ---- scores = Q @ K^T ----
        float s[2][8][4];
#pragma unroll
        for (int mi = 0; mi < 2; ++mi)
#pragma unroll
            for (int ni = 0; ni < 8; ++ni) {
                s[mi][ni][0]=0.f; s[mi][ni][1]=0.f; s[mi][ni][2]=0.f; s[mi][ni][3]=0.f;
            }
#pragma unroll
        for (int ks = 0; ks < 4; ++ks) {
            const int kb2 = ks*32;
            uint32_t a0[4], a1[4], kf[4][4];
            LDM4(a0[0], a0[1], a0[2], a0[3], qb0 + kb2);
            LDM4(a1[0], a1[1], a1[2], a1[3], qb1 + kb2);
#pragma unroll
            for (int j = 0; j < 4; ++j)
                LDM4(kf[j][0], kf[j][1], kf[j][2], kf[j][3], kpb + j*16*KST*2 + kb2);
#pragma unroll
            for (int j = 0; j < 4; ++j) {
                uint32_t be[2] = {kf[j][0], kf[j][2]};
                uint32_t bo2[2] = {kf[j][1], kf[j][3]};
                mma16(s[0][2*j],   a0, be);
                mma16(s[1][2*j],   a1, be);
                mma16(s[0][2*j+1], a0, bo2);
                mma16(s[1][2*j+1], a1, bo2);
            }
        }

        // ---- exp2 + row-sums ----
#pragma unroll
        for (int mi = 0; mi < 2; ++mi) {
            float rs0 = 0.f, rs1 = 0.f;
#pragma unroll
            for (int ni = 0; ni < 8; ++ni) {
                float m0 = mb[ni*8 + 2*c]     ? -1e30f : 0.f;
                float m1 = mb[ni*8 + 2*c + 1] ? -1e30f : 0.f;
                s[mi][ni][0] = fex2(s[mi][ni][0] + m0);
                s[mi][ni][1] = fex2(s[mi][ni][1] + m1);
                s[mi][ni][2] = fex2(s[mi][ni][2] + m0);
                s[mi][ni][3] = fex2(s[mi][ni][3] + m1);
                rs0 += s[mi][ni][0] + s[mi][ni][1];
                rs1 += s[mi][ni][2] + s[mi][ni][3];
            }
            rs0 += __shfl_xor_sync(0xffffffffu, rs0, 1);
            rs0 += __shfl_xor_sync(0xffffffffu, rs0, 2);
            rs1 += __shfl_xor_sync(0xffffffffu, rs1, 1);
            rs1 += __shfl_xor_sync(0xffffffffu, rs1, 2);
            l[mi][0] += rs0; l[mi][1] += rs1;
        }

        // ---- o += P @ V^T ----
#pragma unroll
        for (int kc = 0; kc < 4; ++kc) {
            uint32_t ap[2][4], vf[4][4];
#pragma unroll
            for (int mi = 0; mi < 2; ++mi) {
                ap[mi][0] = h2u(s[mi][2*kc][0],   s[mi][2*kc][1]);
                ap[mi][1] = h2u(s[mi][2*kc][2],   s[mi][2*kc][3]);
                ap[mi][2] = h2u(s[mi][2*kc+1][0], s[mi][2*kc+1][1]);
                ap[mi][3] = h2u(s[mi][2*kc+1][2], s[mi][2*kc+1][3]);
            }
#pragma unroll
            for (int j = 0; j < 4; ++j)
                LDM4(vf[j][0], vf[j][1], vf[j][2], vf[j][3], vpb + j*16*KST*2 + kc*32);
#pragma unroll
            for (int j = 0; j < 4; ++j) {
                uint32_t be[2] = {vf[j][0], vf[j][2]};
                uint32_t bo2[2] = {vf[j][1], vf[j][3]};
                mma16(o[0][2*j],   ap[0], be);
                mma16(o[1][2*j],   ap[1], be);
                mma16(o[0][2*j+1], ap[0], bo2);
                mma16(o[1][2*j+1], ap[1], bo2);
            }
        }
        __syncthreads();
    }

    // ---- epilogue ----
    __half* Op = p ? g_O1h : g_O0h;
#pragma unroll
    for (int mi = 0; mi < 2; ++mi) {
        const int r0 = q0 + wrow + mi*16 + g, r1 = r0 + 8;
        const float inv0 = pw / l[mi][0], inv1 = pw / l[mi][1];
#pragma unroll
        for (int ni = 0; ni < 8; ++ni) {
            int col = hoff + ni*8 + 2*c;
            size_t i0 = (size_t)(b*SS + r0)*EE + col;
            size_t i1 = (size_t)(b*SS + r1)*EE + col;
            float v0 = o[mi][ni][0]*inv0, v1 = o[mi][ni][1]*inv0;
            float v2 = o[mi][ni][2]*inv1, v3 = o[mi][ni][3]*inv1;
            if (r0 >= 1) {
                __half2 gh = *(const __half2*)&g_Gh[i0];
                v0 *= __half2float(gh.x);
                v1 *= __half2float(gh.y);
            }
            __half2 gw = *(const __half2*)&g_Gh[i1];
            v2 *= __half2float(gw.x);
            v3 *= __half2float(gw.y);
            *(__half2*)&Op[i0] = __floats2half2_rn(v0, v1);
            *(__half2*)&Op[i1] = __floats2half2_rn(v2, v3);
        }
    }
}

// ---------------- launch ----------------
extern "C" void kernel_launch(void* const* d_in, const int* in_sizes, int n_in,
                              void* d_out, int out_size)
{
    const float* x  = (const float*)d_in[0];
    const float* Wq = (const float*)d_in[1];
    const float* bq = (const float*)d_in[2];
    const float* Wk = (const float*)d_in[3];
    const float* bk = (const float*)d_in[4];
    const float* Wv = (const float*)d_in[5];
    const float* bv = (const float*)d_in[6];
    const float* Wo = (const float*)d_in[7];
    const float* bo = (const float*)d_in[8];
    const float* Wg = (const float*)d_in[9];
    const unsigned char* mask = (const unsigned char*)d_in[10];
    float* out = (float*)d_out;

    static int attr_set = 0;
    if (!attr_set) {
        cudaFuncSetAttribute(gemm_qkvg, cudaFuncAttributeMaxDynamicSharedMemorySize, GEMM_SMEM);
        cudaFuncSetAttribute(gemm_out,  cudaFuncAttributeMaxDynamicSharedMemorySize, GEMM_SMEM);
        cudaFuncSetAttribute(attn_h,    cudaFuncAttributeMaxDynamicSharedMemorySize, ATT_SMEM);
        attr_set = 1;
    }

    prep_x<<<MM*EE/512, 256>>>(x);
    prep_w<<<dim3(32, 32, 5), dim3(32, 8)>>>(Wq, Wk, Wv, Wg, Wo);
    gemm_qkvg<<<dim3(8, 32, 4), 128, GEMM_SMEM>>>(bq, bk, bv);
    attn_h<<<dim3(SS/128, HH, BB*2), 128, ATT_SMEM>>>(mask);
    sum_o<<<MM*EE/512, 256>>>();
    gemm_out<<<dim3(8, 32), 128, GEMM_SMEM>>>(bo, out);
}

// round 12
// speedup vs baseline: 1.0834x; 1.0834x over previous
#include <cuda_runtime.h>
#include <cuda_fp16.h>
#include <cstdint>

#define BB 2
#define SS 2048
#define EE 1024
#define HH 16
#define DD 64
#define MM (BB*SS)
#define SCALE 0.125f
#define LOG2E 1.44269504f
#define GK 1024
#define GN 1024

// ---------------- scratch ----------------
__device__ __half g_Xh[MM*EE];
__device__ __half g_WT[5][EE*EE];   // 0=q 1=k 2=v 3=g 4=o, [n][k]
__device__ __half g_Qh[MM*EE];
__device__ __half g_Kh[MM*EE];
__device__ __half g_Vt[MM*EE];      // [b][h][d][tok]
__device__ __half g_Gh[MM*EE];      // sigmoid(gate), half
__device__ __half g_O0h[MM*EE];
__device__ __half g_O1h[MM*EE];
__device__ __half g_Oh[MM*EE];

// ---------------- helpers ----------------
__device__ __forceinline__ uint32_t smem_u32(const void* p) {
    return (uint32_t)__cvta_generic_to_shared(p);
}
#define CP16(d_, s_) asm volatile("cp.async.cg.shared.global [%0],[%1],16;\n" :: "r"(d_), "l"(s_))
#define CPCOMMIT() asm volatile("cp.async.commit_group;\n")
#define CPWAIT1() asm volatile("cp.async.wait_group 1;\n")
#define CPWAIT0() asm volatile("cp.async.wait_group 0;\n")

__device__ __forceinline__ void mma16(float* d, const uint32_t* a, const uint32_t* b) {
    asm volatile(
        "mma.sync.aligned.m16n8k16.row.col.f32.f16.f16.f32 "
        "{%0,%1,%2,%3}, {%4,%5,%6,%7}, {%8,%9}, {%0,%1,%2,%3};"
        : "+f"(d[0]), "+f"(d[1]), "+f"(d[2]), "+f"(d[3])
        : "r"(a[0]), "r"(a[1]), "r"(a[2]), "r"(a[3]), "r"(b[0]), "r"(b[1]));
}
__device__ __forceinline__ uint32_t h2u(float x, float y) {
    __half2 h = __floats2half2_rn(x, y);
    return *(uint32_t*)&h;
}
__device__ __forceinline__ float fex2(float x) {
    float y; asm("ex2.approx.f32 %0, %1;" : "=f"(y) : "f"(x)); return y;
}

// ---------------- prep ----------------
__global__ void prep_x(const float* __restrict__ x) {
    int i = blockIdx.x * 256 + threadIdx.x;
    float2 v = ((const float2*)x)[i];
    ((__half2*)g_Xh)[i] = __floats2half2_rn(v.x, v.y);
}
__global__ void prep_w(const float* Wq, const float* Wk, const float* Wv,
                       const float* Wg, const float* Wo) {
    __shared__ float t[32][33];
    int z = blockIdx.z;
    const float* W = z==0?Wq : z==1?Wk : z==2?Wv : z==3?Wg : Wo;
    __half* D = g_WT[z];
    int n0 = blockIdx.x*32, k0 = blockIdx.y*32;
    int tx = threadIdx.x, ty = threadIdx.y;
#pragma unroll
    for (int j = 0; j < 4; ++j)
        t[ty + j*8][tx] = W[(size_t)(k0 + ty + j*8)*GN + n0 + tx];
    __syncthreads();
#pragma unroll
    for (int j = 0; j < 4; ++j)
        D[(size_t)(n0 + ty + j*8)*GK + k0 + tx] = __float2half_rn(t[tx][ty + j*8]);
}
__global__ void sum_o() {
    int i = blockIdx.x * 256 + threadIdx.x;
    ((__half2*)g_Oh)[i] = __hadd2(((const __half2*)g_O0h)[i], ((const __half2*)g_O1h)[i]);
}

// ---------------- GEMM core: 256 thr, 8 warps (4x2), warp tile 32x64 -------
#define AST 72
#define TILE_H (128*AST)
#define GEMM_SMEM (4*TILE_H*2)

__device__ __forceinline__ void gemm_core(
    const __half* __restrict__ A, const __half* __restrict__ Bt,
    const float* __restrict__ bias, float* __restrict__ fC,
    __half* __restrict__ hC, int mode)
{
    extern __shared__ char smp[];
    __half* As = (__half*)smp;
    __half* Bs = (__half*)smp + 2*TILE_H;

    const int tid = threadIdx.x, lane = tid & 31, wid = tid >> 5;
    const int wm = wid >> 1, wn = wid & 1, g = lane >> 2, c = lane & 3;
    const int row0 = blockIdx.y*128, col0 = blockIdx.x*128;

    float acc[2][8][4];
#pragma unroll
    for (int mi = 0; mi < 2; ++mi)
#pragma unroll
        for (int ni = 0; ni < 8; ++ni) {
            acc[mi][ni][0]=0.f; acc[mi][ni][1]=0.f; acc[mi][ni][2]=0.f; acc[mi][ni][3]=0.f;
        }

    {
#pragma unroll
        for (int u = 0; u < 4; ++u) {
            int idx = tid + u*256, r = idx >> 3, ko = (idx & 7)*8;
            CP16(smem_u32(&As[r*AST + ko]), &A[(size_t)(row0+r)*GK + ko]);
            CP16(smem_u32(&Bs[r*AST + ko]), &Bt[(size_t)(col0+r)*GK + ko]);
        }
        CPCOMMIT();
    }

#pragma unroll 1
    for (int it = 0; it < 16; ++it) {
        if (it < 15) {
            int buf = (it+1) & 1, k0 = (it+1)*64;
#pragma unroll
            for (int u = 0; u < 4; ++u) {
                int idx = tid + u*256, r = idx >> 3, ko = (idx & 7)*8;
                CP16(smem_u32(&As[buf*TILE_H + r*AST + ko]), &A[(size_t)(row0+r)*GK + k0 + ko]);
                CP16(smem_u32(&Bs[buf*TILE_H + r*AST + ko]), &Bt[(size_t)(col0+r)*GK + k0 + ko]);
            }
            CPCOMMIT();
            CPWAIT1();
        } else {
            CPWAIT0();
        }
        __syncthreads();
        const __half* Ab = &As[(it & 1)*TILE_H];
        const __half* Bb = &Bs[(it & 1)*TILE_H];
#pragma unroll
        for (int ks = 0; ks < 4; ++ks) {
            int kb = ks*16;
            uint32_t a[2][4];
#pragma unroll
            for (int mi = 0; mi < 2; ++mi) {
                int r = wm*32 + mi*16 + g;
                a[mi][0] = *(const uint32_t*)&Ab[r*AST + kb + 2*c];
                a[mi][1] = *(const uint32_t*)&Ab[(r+8)*AST + kb + 2*c];
                a[mi][2] = *(const uint32_t*)&Ab[r*AST + kb + 8 + 2*c];
                a[mi][3] = *(const uint32_t*)&Ab[(r+8)*AST + kb + 8 + 2*c];
            }
#pragma unroll
            for (int ni = 0; ni < 8; ++ni) {
                int n = wn*64 + ni*8 + g;
                uint32_t b[2];
                b[0] = *(const uint32_t*)&Bb[n*AST + kb + 2*c];
                b[1] = *(const uint32_t*)&Bb[n*AST + kb + 8 + 2*c];
                mma16(acc[0][ni], a[0], b);
                mma16(acc[1][ni], a[1], b);
            }
        }
        __syncthreads();
    }

#pragma unroll
    for (int mi = 0; mi < 2; ++mi) {
#pragma unroll
        for (int ni = 0; ni < 8; ++ni) {
            int r = row0 + wm*32 + mi*16 + g;
            int col = col0 + wn*64 + ni*8 + 2*c;
            float b0 = 0.f, b1 = 0.f;
            if (bias) { b0 = bias[col]; b1 = bias[col+1]; }
            float v0 = acc[mi][ni][0]+b0, v1 = acc[mi][ni][1]+b1;
            float v2 = acc[mi][ni][2]+b0, v3 = acc[mi][ni][3]+b1;
            if (mode == 0) {
                const float f = SCALE * LOG2E;
                v0*=f; v1*=f; v2*=f; v3*=f;
            }
            if (mode == 4) {
                *(float2*)&fC[(size_t)r*GN + col] = make_float2(v0, v1);
                *(float2*)&fC[(size_t)(r+8)*GN + col] = make_float2(v2, v3);
            } else if (mode == 3) {
                float s0 = 1.f/(1.f+__expf(-v0)), s1 = 1.f/(1.f+__expf(-v1));
                float s2 = 1.f/(1.f+__expf(-v2)), s3 = 1.f/(1.f+__expf(-v3));
                *(__half2*)&hC[(size_t)r*GN + col] = __floats2half2_rn(s0, s1);
                *(__half2*)&hC[(size_t)(r+8)*GN + col] = __floats2half2_rn(s2, s3);
            } else if (mode == 2) {
                int bi = r >> 11, tok = r & 2047, hh = col >> 6, d = col & 63;
                __half* Vb = &g_Vt[(size_t)((bi*HH + hh)*DD) * SS];
                Vb[(size_t)d*SS + tok]       = __float2half_rn(v0);
                Vb[(size_t)(d+1)*SS + tok]   = __float2half_rn(v1);
                Vb[(size_t)d*SS + tok+8]     = __float2half_rn(v2);
                Vb[(size_t)(d+1)*SS + tok+8] = __float2half_rn(v3);
            } else {
                *(__half2*)&hC[(size_t)r*GN + col] = __floats2half2_rn(v0, v1);
                *(__half2*)&hC[(size_t)(r+8)*GN + col] = __floats2half2_rn(v2, v3);
            }
        }
    }
}

__global__ __launch_bounds__(256, 2) void gemm_qkvg(
    const float* bq, const float* bk, const float* bv)
{
    int z = blockIdx.z;
    const float* bias = z==0?bq : z==1?bk : z==2?bv : nullptr;
    __half* hC = z==0?g_Qh : z==1?g_Kh : z==2?nullptr : g_Gh;
    gemm_core(g_Xh, g_WT[z], bias, nullptr, hC, z);
}
__global__ __launch_bounds__(256, 2) void gemm_out(const float* bo, float* out)
{
    gemm_core(g_Oh, g_WT[4], bo, out, nullptr, 4);
}

// ---------------- Attention (R8, unchanged): mi=2 register-P flash ----------
#define KST 72
#define Q_OFF 0
#define K_OFF (128*KST)
#define V_OFF (K_OFF + 2*64*KST)
#define MSK_OFF_B ((V_OFF + 2*64*KST)*2)
#define ATT_SMEM (MSK_OFF_B + 128)

__global__ __launch_bounds__(128) void attn_h(const unsigned char* __restrict__ mask)
{
    extern __shared__ char smc[];
    __half* Qs = (__half*)smc + Q_OFF;
    __half* Ks = (__half*)smc + K_OFF;
    __half* Vs = (__half*)smc + V_OFF;
    unsigned char* mskb = (unsigned char*)smc + MSK_OFF_B;

    const int tid = threadIdx.x, lane = tid & 31, wid = tid >> 5;
    const int g = lane >> 2, c = lane & 3;
    const int h = blockIdx.y, z = blockIdx.z;
    const int b = z >> 1, p = z & 1;
    const int q0 = blockIdx.x*128, hoff = h*DD;
    const int kbase = p*1024;
    const float pw = p ? 1.0f : 0.5f;
    const int wrow = wid*32;
    const __half* Kg = &g_Kh[(size_t)b*SS*EE + hoff];
    const __half* Vg = &g_Vt[(size_t)(b*HH + h)*DD*SS];

    auto issue = [&](int t) {
        int buf = t & 1, k0g = kbase + t*64;
#pragma unroll
        for (int u = 0; u < 4; ++u) {
            int idx = tid + u*128, r = idx >> 3, ko = (idx & 7)*8;
            CP16(smem_u32(&Ks[buf*64*KST + r*KST + ko]), &Kg[(size_t)(k0g + r)*EE + ko]);
            CP16(smem_u32(&Vs[buf*64*KST + r*KST + ko]), &Vg[(size_t)r*SS + k0g + ko]);
        }
        if (tid < 4)
            CP16(smem_u32(&mskb[(t & 1)*64 + tid*16]), &mask[(size_t)b*SS + k0g + tid*16]);
        CPCOMMIT();
    };

#pragma unroll
    for (int u = 0; u < 8; ++u) {
        int idx = tid + u*128, r = idx >> 3, ko = (idx & 7)*8;
        CP16(smem_u32(&Qs[r*KST + ko]), &g_Qh[(size_t)(b*SS + q0 + r)*EE + hoff + ko]);
    }
    issue(0);

    float o[2][8][4];
    float l[2][2] = {{0.f,0.f},{0.f,0.f}};
#pragma unroll
    for (int mi = 0; mi < 2; ++mi)
#pragma unroll
        for (int ni = 0; ni < 8; ++ni) {
            o[mi][ni][0]=0.f; o[mi][ni][1]=0.f; o[mi][ni][2]=0.f; o[mi][ni][3]=0.f;
        }

#pragma unroll 1
    for (int t = 0; t < 16; ++t) {
        if (t < 15) { issue(t + 1); CPWAIT1(); } else { CPWAIT0(); }
        __syncthreads();
        const __half* Kb = &Ks[(t & 1)*64*KST];
        const __half* Vb = &Vs[(t & 1)*64*KST];
        const unsigned char* mb = &mskb[(t & 1)*64];

        float s[2][8][4];
#pragma unroll
        for (int mi = 0; mi < 2; ++mi)
#pragma unroll
            for (int ni = 0; ni < 8; ++ni) {
                s[mi][ni][0]=0.f; s[mi][ni][1]=0.f; s[mi][ni][2]=0.f; s[mi][ni][3]=0.f;
            }
#pragma unroll
        for (int ks = 0; ks < 4; ++ks) {
            int kb = ks*16;
            uint32_t a[2][4];
#pragma unroll
            for (int mi = 0; mi < 2; ++mi) {
                int r = wrow + mi*16 + g;
                a[mi][0] = *(const uint32_t*)&Qs[r*KST + kb + 2*c];
                a[mi][1] = *(const uint32_t*)&Qs[(r+8)*KST + kb + 2*c];
                a[mi][2] = *(const uint32_t*)&Qs[r*KST + kb + 8 + 2*c];
                a[mi][3] = *(const uint32_t*)&Qs[(r+8)*KST + kb + 8 + 2*c];
            }
#pragma unroll
            for (int ni = 0; ni < 8; ++ni) {
                int n = ni*8 + g;
                uint32_t bf[2];
                bf[0] = *(const uint32_t*)&Kb[n*KST + kb + 2*c];
                bf[1] = *(const uint32_t*)&Kb[n*KST + kb + 8 + 2*c];
                mma16(s[0][ni], a[0], bf);
                mma16(s[1][ni], a[1], bf);
            }
        }

#pragma unroll
        for (int mi = 0; mi < 2; ++mi) {
            float rs0 = 0.f, rs1 = 0.f;
#pragma unroll
            for (int ni = 0; ni < 8; ++ni) {
                float m0 = mb[ni*8 + 2*c]     ? -1e30f : 0.f;
                float m1 = mb[ni*8 + 2*c + 1] ? -1e30f : 0.f;
                s[mi][ni][0] = fex2(s[mi][ni][0] + m0);
                s[mi][ni][1] = fex2(s[mi][ni][1] + m1);
                s[mi][ni][2] = fex2(s[mi][ni][2] + m0);
                s[mi][ni][3] = fex2(s[mi][ni][3] + m1);
                rs0 += s[mi][ni][0] + s[mi][ni][1];
                rs1 += s[mi][ni][2] + s[mi][ni][3];
            }
            rs0 += __shfl_xor_sync(0xffffffffu, rs0, 1);
            rs0 += __shfl_xor_sync(0xffffffffu, rs0, 2);
            rs1 += __shfl_xor_sync(0xffffffffu, rs1, 1);
            rs1 += __shfl_xor_sync(0xffffffffu, rs1, 2);
            l[mi][0] += rs0; l[mi][1] += rs1;
        }

#pragma unroll
        for (int kc = 0; kc < 4; ++kc) {
            uint32_t ap[2][4];
#pragma unroll
            for (int mi = 0; mi < 2; ++mi) {
                ap[mi][0] = h2u(s[mi][2*kc][0],   s[mi][2*kc][1]);
                ap[mi][1] = h2u(s[mi][2*kc][2],   s[mi][2*kc][3]);
                ap[mi][2] = h2u(s[mi][2*kc+1][0], s[mi][2*kc+1][1]);
                ap[mi][3] = h2u(s[mi][2*kc+1][2], s[mi][2*kc+1][3]);
            }
#pragma unroll
            for (int ni = 0; ni < 8; ++ni) {
                int n = ni*8 + g;
                uint32_t bf[2];
                bf[0] = *(const uint32_t*)&Vb[n*KST + kc*16 + 2*c];
                bf[1] = *(const uint32_t*)&Vb[n*KST + kc*16 + 8 + 2*c];
                mma16(o[0][ni], ap[0], bf);
                mma16(o[1][ni], ap[1], bf);
            }
        }
        __syncthreads();
    }

    __half* Op = p ? g_O1h : g_O0h;
#pragma unroll
    for (int mi = 0; mi < 2; ++mi) {
        const int r0 = q0 + wrow + mi*16 + g, r1 = r0 + 8;
        const float inv0 = pw / l[mi][0], inv1 = pw / l[mi][1];
#pragma unroll
        for (int ni = 0; ni < 8; ++ni) {
            int col = hoff + ni*8 + 2*c;
            size_t i0 = (size_t)(b*SS + r0)*EE + col;
            size_t i1 = (size_t)(b*SS + r1)*EE + col;
            float v0 = o[mi][ni][0]*inv0, v1 = o[mi][ni][1]*inv0;
            float v2 = o[mi][ni][2]*inv1, v3 = o[mi][ni][3]*inv1;
            if (r0 >= 1) {
                __half2 gh = *(const __half2*)&g_Gh[i0];
                v0 *= __half2float(gh.x);
                v1 *= __half2float(gh.y);
            }
            __half2 gw = *(const __half2*)&g_Gh[i1];
            v2 *= __half2float(gw.x);
            v3 *= __half2float(gw.y);
            *(__half2*)&Op[i0] = __floats2half2_rn(v0, v1);
            *(__half2*)&Op[i1] = __floats2half2_rn(v2, v3);
        }
    }
}

// ---------------- launch ----------------
extern "C" void kernel_launch(void* const* d_in, const int* in_sizes, int n_in,
                              void* d_out, int out_size)
{
    const float* x  = (const float*)d_in[0];
    const float* Wq = (const float*)d_in[1];
    const float* bq = (const float*)d_in[2];
    const float* Wk = (const float*)d_in[3];
    const float* bk = (const float*)d_in[4];
    const float* Wv = (const float*)d_in[5];
    const float* bv = (const float*)d_in[6];
    const float* Wo = (const float*)d_in[7];
    const float* bo = (const float*)d_in[8];
    const float* Wg = (const float*)d_in[9];
    const unsigned char* mask = (const unsigned char*)d_in[10];
    float* out = (float*)d_out;

    static int attr_set = 0;
    if (!attr_set) {
        cudaFuncSetAttribute(gemm_qkvg, cudaFuncAttributeMaxDynamicSharedMemorySize, GEMM_SMEM);
        cudaFuncSetAttribute(gemm_out,  cudaFuncAttributeMaxDynamicSharedMemorySize, GEMM_SMEM);
        cudaFuncSetAttribute(attn_h,    cudaFuncAttributeMaxDynamicSharedMemorySize, ATT_SMEM);
        attr_set = 1;
    }

    prep_x<<<MM*EE/512, 256>>>(x);
    prep_w<<<dim3(32, 32, 5), dim3(32, 8)>>>(Wq, Wk, Wv, Wg, Wo);
    gemm_qkvg<<<dim3(8, 32, 4), 256, GEMM_SMEM>>>(bq, bk, bv);
    attn_h<<<dim3(SS/128, HH, BB*2), 128, ATT_SMEM>>>(mask);
    sum_o<<<MM*EE/512, 256>>>();
    gemm_out<<<dim3(8, 32), 256, GEMM_SMEM>>>(bo, out);
}

// round 13
// speedup vs baseline: 1.0898x; 1.0059x over previous
#include <cuda_runtime.h>
#include <cuda_fp16.h>
#include <cstdint>

#define BB 2
#define SS 2048
#define EE 1024
#define HH 16
#define DD 64
#define MM (BB*SS)
#define SCALE 0.125f
#define LOG2E 1.44269504f
#define GK 1024
#define GN 1024

// ---------------- scratch ----------------
__device__ __half g_Xh[MM*EE];
__device__ __half g_WT[5][EE*EE];   // 0=q 1=k 2=v 3=g 4=o, [n][k]
__device__ __half g_Qh[MM*EE];
__device__ __half g_Kh[MM*EE];
__device__ __half g_Vt[MM*EE];      // [b][h][d][tok]
__device__ __half g_Gh[MM*EE];      // sigmoid(gate), half
__device__ __half g_O0h[MM*EE];
__device__ __half g_O1h[MM*EE];
__device__ __half g_Oh[MM*EE];

// ---------------- helpers ----------------
__device__ __forceinline__ uint32_t smem_u32(const void* p) {
    return (uint32_t)__cvta_generic_to_shared(p);
}
#define CP16(d_, s_) asm volatile("cp.async.cg.shared.global [%0],[%1],16;\n" :: "r"(d_), "l"(s_))
#define CPCOMMIT() asm volatile("cp.async.commit_group;\n")
#define CPWAIT1() asm volatile("cp.async.wait_group 1;\n")
#define CPWAIT0() asm volatile("cp.async.wait_group 0;\n")

__device__ __forceinline__ void mma16(float* d, const uint32_t* a, const uint32_t* b) {
    asm volatile(
        "mma.sync.aligned.m16n8k16.row.col.f32.f16.f16.f32 "
        "{%0,%1,%2,%3}, {%4,%5,%6,%7}, {%8,%9}, {%0,%1,%2,%3};"
        : "+f"(d[0]), "+f"(d[1]), "+f"(d[2]), "+f"(d[3])
        : "r"(a[0]), "r"(a[1]), "r"(a[2]), "r"(a[3]), "r"(b[0]), "r"(b[1]));
}
// f16-accumulator variant: D/C are 2 b32 regs (half2 pairs)
__device__ __forceinline__ void mma16h(uint32_t* d, const uint32_t* a, const uint32_t* b) {
    asm volatile(
        "mma.sync.aligned.m16n8k16.row.col.f16.f16.f16.f16 "
        "{%0,%1}, {%2,%3,%4,%5}, {%6,%7}, {%0,%1};"
        : "+r"(d[0]), "+r"(d[1])
        : "r"(a[0]), "r"(a[1]), "r"(a[2]), "r"(a[3]), "r"(b[0]), "r"(b[1]));
}
__device__ __forceinline__ uint32_t h2ex2(uint32_t x) {
    uint32_t y;
    asm("ex2.approx.f16x2 %0, %1;" : "=r"(y) : "r"(x));
    return y;
}
__device__ __forceinline__ uint32_t h2addu(uint32_t a, uint32_t b) {
    __half2 r = __hadd2(*(__half2*)&a, *(__half2*)&b);
    return *(uint32_t*)&r;
}

// ---------------- prep ----------------
__global__ void prep_x(const float* __restrict__ x) {
    int i = blockIdx.x * 256 + threadIdx.x;
    float2 v = ((const float2*)x)[i];
    ((__half2*)g_Xh)[i] = __floats2half2_rn(v.x, v.y);
}
__global__ void prep_w(const float* Wq, const float* Wk, const float* Wv,
                       const float* Wg, const float* Wo) {
    __shared__ float t[32][33];
    int z = blockIdx.z;
    const float* W = z==0?Wq : z==1?Wk : z==2?Wv : z==3?Wg : Wo;
    __half* D = g_WT[z];
    int n0 = blockIdx.x*32, k0 = blockIdx.y*32;
    int tx = threadIdx.x, ty = threadIdx.y;
#pragma unroll
    for (int j = 0; j < 4; ++j)
        t[ty + j*8][tx] = W[(size_t)(k0 + ty + j*8)*GN + n0 + tx];
    __syncthreads();
#pragma unroll
    for (int j = 0; j < 4; ++j)
        D[(size_t)(n0 + ty + j*8)*GK + k0 + tx] = __float2half_rn(t[tx][ty + j*8]);
}
__global__ void sum_o() {
    int i = blockIdx.x * 256 + threadIdx.x;
    ((__half2*)g_Oh)[i] = __hadd2(((const __half2*)g_O0h)[i], ((const __half2*)g_O1h)[i]);
}

// ---------------- GEMM core: 256 thr, 8 warps (4x2), warp tile 32x64 -------
#define AST 72
#define TILE_H (128*AST)
#define GEMM_SMEM (4*TILE_H*2)

__device__ __forceinline__ void gemm_core(
    const __half* __restrict__ A, const __half* __restrict__ Bt,
    const float* __restrict__ bias, float* __restrict__ fC,
    __half* __restrict__ hC, int mode)
{
    extern __shared__ char smp[];
    __half* As = (__half*)smp;
    __half* Bs = (__half*)smp + 2*TILE_H;

    const int tid = threadIdx.x, lane = tid & 31, wid = tid >> 5;
    const int wm = wid >> 1, wn = wid & 1, g = lane >> 2, c = lane & 3;
    const int row0 = blockIdx.y*128, col0 = blockIdx.x*128;

    float acc[2][8][4];
#pragma unroll
    for (int mi = 0; mi < 2; ++mi)
#pragma unroll
        for (int ni = 0; ni < 8; ++ni) {
            acc[mi][ni][0]=0.f; acc[mi][ni][1]=0.f; acc[mi][ni][2]=0.f; acc[mi][ni][3]=0.f;
        }

    {
#pragma unroll
        for (int u = 0; u < 4; ++u) {
            int idx = tid + u*256, r = idx >> 3, ko = (idx & 7)*8;
            CP16(smem_u32(&As[r*AST + ko]), &A[(size_t)(row0+r)*GK + ko]);
            CP16(smem_u32(&Bs[r*AST + ko]), &Bt[(size_t)(col0+r)*GK + ko]);
        }
        CPCOMMIT();
    }

#pragma unroll 1
    for (int it = 0; it < 16; ++it) {
        if (it < 15) {
            int buf = (it+1) & 1, k0 = (it+1)*64;
#pragma unroll
            for (int u = 0; u < 4; ++u) {
                int idx = tid + u*256, r = idx >> 3, ko = (idx & 7)*8;
                CP16(smem_u32(&As[buf*TILE_H + r*AST + ko]), &A[(size_t)(row0+r)*GK + k0 + ko]);
                CP16(smem_u32(&Bs[buf*TILE_H + r*AST + ko]), &Bt[(size_t)(col0+r)*GK + k0 + ko]);
            }
            CPCOMMIT();
            CPWAIT1();
        } else {
            CPWAIT0();
        }
        __syncthreads();
        const __half* Ab = &As[(it & 1)*TILE_H];
        const __half* Bb = &Bs[(it & 1)*TILE_H];
#pragma unroll
        for (int ks = 0; ks < 4; ++ks) {
            int kb = ks*16;
            uint32_t a[2][4];
#pragma unroll
            for (int mi = 0; mi < 2; ++mi) {
                int r = wm*32 + mi*16 + g;
                a[mi][0] = *(const uint32_t*)&Ab[r*AST + kb + 2*c];
                a[mi][1] = *(const uint32_t*)&Ab[(r+8)*AST + kb + 2*c];
                a[mi][2] = *(const uint32_t*)&Ab[r*AST + kb + 8 + 2*c];
                a[mi][3] = *(const uint32_t*)&Ab[(r+8)*AST + kb + 8 + 2*c];
            }
#pragma unroll
            for (int ni = 0; ni < 8; ++ni) {
                int n = wn*64 + ni*8 + g;
                uint32_t b[2];
                b[0] = *(const uint32_t*)&Bb[n*AST + kb + 2*c];
                b[1] = *(const uint32_t*)&Bb[n*AST + kb + 8 + 2*c];
                mma16(acc[0][ni], a[0], b);
                mma16(acc[1][ni], a[1], b);
            }
        }
        __syncthreads();
    }

#pragma unroll
    for (int mi = 0; mi < 2; ++mi) {
#pragma unroll
        for (int ni = 0; ni < 8; ++ni) {
            int r = row0 + wm*32 + mi*16 + g;
            int col = col0 + wn*64 + ni*8 + 2*c;
            float b0 = 0.f, b1 = 0.f;
            if (bias) { b0 = bias[col]; b1 = bias[col+1]; }
            float v0 = acc[mi][ni][0]+b0, v1 = acc[mi][ni][1]+b1;
            float v2 = acc[mi][ni][2]+b0, v3 = acc[mi][ni][3]+b1;
            if (mode == 0) {
                const float f = SCALE * LOG2E;
                v0*=f; v1*=f; v2*=f; v3*=f;
            }
            if (mode == 4) {
                *(float2*)&fC[(size_t)r*GN + col] = make_float2(v0, v1);
                *(float2*)&fC[(size_t)(r+8)*GN + col] = make_float2(v2, v3);
            } else if (mode == 3) {
                float s0 = 1.f/(1.f+__expf(-v0)), s1 = 1.f/(1.f+__expf(-v1));
                float s2 = 1.f/(1.f+__expf(-v2)), s3 = 1.f/(1.f+__expf(-v3));
                *(__half2*)&hC[(size_t)r*GN + col] = __floats2half2_rn(s0, s1);
                *(__half2*)&hC[(size_t)(r+8)*GN + col] = __floats2half2_rn(s2, s3);
            } else if (mode == 2) {
                int bi = r >> 11, tok = r & 2047, hh = col >> 6, d = col & 63;
                __half* Vb = &g_Vt[(size_t)((bi*HH + hh)*DD) * SS];
                Vb[(size_t)d*SS + tok]       = __float2half_rn(v0);
                Vb[(size_t)(d+1)*SS + tok]   = __float2half_rn(v1);
                Vb[(size_t)d*SS + tok+8]     = __float2half_rn(v2);
                Vb[(size_t)(d+1)*SS + tok+8] = __float2half_rn(v3);
            } else {
                *(__half2*)&hC[(size_t)r*GN + col] = __floats2half2_rn(v0, v1);
                *(__half2*)&hC[(size_t)(r+8)*GN + col] = __floats2half2_rn(v2, v3);
            }
        }
    }
}

__global__ __launch_bounds__(256, 2) void gemm_qkvg(
    const float* bq, const float* bk, const float* bv)
{
    int z = blockIdx.z;
    const float* bias = z==0?bq : z==1?bk : z==2?bv : nullptr;
    __half* hC = z==0?g_Qh : z==1?g_Kh : z==2?nullptr : g_Gh;
    gemm_core(g_Xh, g_WT[z], bias, nullptr, hC, z);
}
__global__ __launch_bounds__(256, 2) void gemm_out(const float* bo, float* out)
{
    gemm_core(g_Oh, g_WT[4], bo, out, nullptr, 4);
}

// ---------------- Attention: f16-score flash, mma row-sums ----------------
// Grid (S/128, H, B*2). 128 threads (4 warps), warp = 32 q rows, 64-key tiles.
#define KST 72
#define Q_OFF 0
#define K_OFF (128*KST)
#define V_OFF (K_OFF + 2*64*KST)
#define MSK_OFF_B ((V_OFF + 2*64*KST)*2)
#define ATT_SMEM (MSK_OFF_B + 128)
#define HINF 0xFC00u        // half -inf
#define HONE2 0x3C003C00u   // half2 (1.0, 1.0)

__global__ __launch_bounds__(128) void attn_h(const unsigned char* __restrict__ mask)
{
    extern __shared__ char smc[];
    __half* Qs = (__half*)smc + Q_OFF;
    __half* Ks = (__half*)smc + K_OFF;
    __half* Vs = (__half*)smc + V_OFF;
    unsigned char* mskb = (unsigned char*)smc + MSK_OFF_B;

    const int tid = threadIdx.x, lane = tid & 31, wid = tid >> 5;
    const int g = lane >> 2, c = lane & 3;
    const int h = blockIdx.y, z = blockIdx.z;
    const int b = z >> 1, p = z & 1;
    const int q0 = blockIdx.x*128, hoff = h*DD;
    const int kbase = p*1024;
    const float pw = p ? 1.0f : 0.5f;
    const int wrow = wid*32;
    const __half* Kg = &g_Kh[(size_t)b*SS*EE + hoff];
    const __half* Vg = &g_Vt[(size_t)(b*HH + h)*DD*SS];

    auto issue = [&](int t) {
        int buf = t & 1, k0g = kbase + t*64;
#pragma unroll
        for (int u = 0; u < 4; ++u) {
            int idx = tid + u*128, r = idx >> 3, ko = (idx & 7)*8;
            CP16(smem_u32(&Ks[buf*64*KST + r*KST + ko]), &Kg[(size_t)(k0g + r)*EE + ko]);
            CP16(smem_u32(&Vs[buf*64*KST + r*KST + ko]), &Vg[(size_t)r*SS + k0g + ko]);
        }
        if (tid < 4)
            CP16(smem_u32(&mskb[(t & 1)*64 + tid*16]), &mask[(size_t)b*SS + k0g + tid*16]);
        CPCOMMIT();
    };

#pragma unroll
    for (int u = 0; u < 8; ++u) {
        int idx = tid + u*128, r = idx >> 3, ko = (idx & 7)*8;
        CP16(smem_u32(&Qs[r*KST + ko]), &g_Qh[(size_t)(b*SS + q0 + r)*EE + hoff + ko]);
    }
    issue(0);

    float o[2][8][4];
    float lac[2][4];
#pragma unroll
    for (int mi = 0; mi < 2; ++mi) {
        lac[mi][0]=0.f; lac[mi][1]=0.f; lac[mi][2]=0.f; lac[mi][3]=0.f;
#pragma unroll
        for (int ni = 0; ni < 8; ++ni) {
            o[mi][ni][0]=0.f; o[mi][ni][1]=0.f; o[mi][ni][2]=0.f; o[mi][ni][3]=0.f;
        }
    }
    const uint32_t ones2[2] = {HONE2, HONE2};

#pragma unroll 1
    for (int t = 0; t < 16; ++t) {
        if (t < 15) { issue(t + 1); CPWAIT1(); } else { CPWAIT0(); }
        __syncthreads();
        const __half* Kb = &Ks[(t & 1)*64*KST];
        const __half* Vb = &Vs[(t & 1)*64*KST];
        const unsigned char* mb = &mskb[(t & 1)*64];

        // ---- scores = Q @ K^T, f16 accumulators ----
        uint32_t s[2][8][2];
#pragma unroll
        for (int mi = 0; mi < 2; ++mi)
#pragma unroll
            for (int ni = 0; ni < 8; ++ni) { s[mi][ni][0]=0u; s[mi][ni][1]=0u; }
#pragma unroll
        for (int ks = 0; ks < 4; ++ks) {
            int kb = ks*16;
            uint32_t a[2][4];
#pragma unroll
            for (int mi = 0; mi < 2; ++mi) {
                int r = wrow + mi*16 + g;
                a[mi][0] = *(const uint32_t*)&Qs[r*KST + kb + 2*c];
                a[mi][1] = *(const uint32_t*)&Qs[(r+8)*KST + kb + 2*c];
                a[mi][2] = *(const uint32_t*)&Qs[r*KST + kb + 8 + 2*c];
                a[mi][3] = *(const uint32_t*)&Qs[(r+8)*KST + kb + 8 + 2*c];
            }
#pragma unroll
            for (int ni = 0; ni < 8; ++ni) {
                int n = ni*8 + g;
                uint32_t bf[2];
                bf[0] = *(const uint32_t*)&Kb[n*KST + kb + 2*c];
                bf[1] = *(const uint32_t*)&Kb[n*KST + kb + 8 + 2*c];
                mma16h(s[0][ni], a[0], bf);
                mma16h(s[1][ni], a[1], bf);
            }
        }

        // ---- mask (half2 -inf) + exp2 (SIMD f16x2) ----
        uint32_t mh[8];
#pragma unroll
        for (int ni = 0; ni < 8; ++ni)
            mh[ni] = (mb[ni*8 + 2*c] ? HINF : 0u) | (mb[ni*8 + 2*c + 1] ? (HINF << 16) : 0u);
#pragma unroll
        for (int mi = 0; mi < 2; ++mi)
#pragma unroll
            for (int ni = 0; ni < 8; ++ni) {
                s[mi][ni][0] = h2ex2(h2addu(s[mi][ni][0], mh[ni]));
                s[mi][ni][1] = h2ex2(h2addu(s[mi][ni][1], mh[ni]));
            }

        // ---- o += P @ V^T; row-sums via ones-mma (f32, exact) ----
#pragma unroll
        for (int kc = 0; kc < 4; ++kc) {
            uint32_t ap[2][4];
#pragma unroll
            for (int mi = 0; mi < 2; ++mi) {
                ap[mi][0] = s[mi][2*kc][0];
                ap[mi][1] = s[mi][2*kc][1];
                ap[mi][2] = s[mi][2*kc+1][0];
                ap[mi][3] = s[mi][2*kc+1][1];
            }
#pragma unroll
            for (int ni = 0; ni < 8; ++ni) {
                int n = ni*8 + g;
                uint32_t bf[2];
                bf[0] = *(const uint32_t*)&Vb[n*KST + kc*16 + 2*c];
                bf[1] = *(const uint32_t*)&Vb[n*KST + kc*16 + 8 + 2*c];
                mma16(o[0][ni], ap[0], bf);
                mma16(o[1][ni], ap[1], bf);
            }
            mma16(lac[0], ap[0], ones2);
            mma16(lac[1], ap[1], ones2);
        }
        __syncthreads();
    }

    // ---- epilogue: normalize (l from ones-mma), gate, write half ----
    __half* Op = p ? g_O1h : g_O0h;
#pragma unroll
    for (int mi = 0; mi < 2; ++mi) {
        const int r0 = q0 + wrow + mi*16 + g, r1 = r0 + 8;
        const float inv0 = pw / lac[mi][0], inv1 = pw / lac[mi][2];
#pragma unroll
        for (int ni = 0; ni < 8; ++ni) {
            int col = hoff + ni*8 + 2*c;
            size_t i0 = (size_t)(b*SS + r0)*EE + col;
            size_t i1 = (size_t)(b*SS + r1)*EE + col;
            float v0 = o[mi][ni][0]*inv0, v1 = o[mi][ni][1]*inv0;
            float v2 = o[mi][ni][2]*inv1, v3 = o[mi][ni][3]*inv1;
            if (r0 >= 1) {
                __half2 gh = *(const __half2*)&g_Gh[i0];
                v0 *= __half2float(gh.x);
                v1 *= __half2float(gh.y);
            }
            __half2 gw = *(const __half2*)&g_Gh[i1];
            v2 *= __half2float(gw.x);
            v3 *= __half2float(gw.y);
            *(__half2*)&Op[i0] = __floats2half2_rn(v0, v1);
            *(__half2*)&Op[i1] = __floats2half2_rn(v2, v3);
        }
    }
}

// ---------------- launch ----------------
extern "C" void kernel_launch(void* const* d_in, const int* in_sizes, int n_in,
                              void* d_out, int out_size)
{
    const float* x  = (const float*)d_in[0];
    const float* Wq = (const float*)d_in[1];
    const float* bq = (const float*)d_in[2];
    const float* Wk = (const float*)d_in[3];
    const float* bk = (const float*)d_in[4];
    const float* Wv = (const float*)d_in[5];
    const float* bv = (const float*)d_in[6];
    const float* Wo = (const float*)d_in[7];
    const float* bo = (const float*)d_in[8];
    const float* Wg = (const float*)d_in[9];
    const unsigned char* mask = (const unsigned char*)d_in[10];
    float* out = (float*)d_out;

    static int attr_set = 0;
    if (!attr_set) {
        cudaFuncSetAttribute(gemm_qkvg, cudaFuncAttributeMaxDynamicSharedMemorySize, GEMM_SMEM);
        cudaFuncSetAttribute(gemm_out,  cudaFuncAttributeMaxDynamicSharedMemorySize, GEMM_SMEM);
        cudaFuncSetAttribute(attn_h,    cudaFuncAttributeMaxDynamicSharedMemorySize, ATT_SMEM);
        attr_set = 1;
    }

    prep_x<<<MM*EE/512, 256>>>(x);
    prep_w<<<dim3(32, 32, 5), dim3(32, 8)>>>(Wq, Wk, Wv, Wg, Wo);
    gemm_qkvg<<<dim3(8, 32, 4), 256, GEMM_SMEM>>>(bq, bk, bv);
    attn_h<<<dim3(SS/128, HH, BB*2), 128, ATT_SMEM>>>(mask);
    sum_o<<<MM*EE/512, 256>>>();
    gemm_out<<<dim3(8, 32), 256, GEMM_SMEM>>>(bo, out);
}

// round 16
// speedup vs baseline: 1.1135x; 1.0218x over previous
#include <cuda_runtime.h>
#include <cuda_fp16.h>
#include <cstdint>

#define BB 2
#define SS 2048
#define EE 1024
#define HH 16
#define DD 64
#define MM (BB*SS)
#define SCALE 0.125f
#define LOG2E 1.44269504f
#define GK 1024
#define GN 1024

// ---------------- scratch ----------------
__device__ __half g_Xh[MM*EE];
__device__ __half g_WT[5][EE*EE];   // 0=q 1=k 2=v 3=g 4=o, [n][k]
__device__ __half g_Qh[MM*EE];
__device__ __half g_Kh[MM*EE];
__device__ __half g_Vt[MM*EE];      // [b][h][d][tok]
__device__ __half g_Gh[MM*EE];      // sigmoid(gate), half
__device__ __half g_O0h[MM*EE];
__device__ __half g_O1h[MM*EE];

// ---------------- helpers ----------------
__device__ __forceinline__ uint32_t smem_u32(const void* p) {
    return (uint32_t)__cvta_generic_to_shared(p);
}
#define CP16(d_, s_) asm volatile("cp.async.cg.shared.global [%0],[%1],16;\n" :: "r"(d_), "l"(s_))
#define CPCOMMIT() asm volatile("cp.async.commit_group;\n")
#define CPWAIT1() asm volatile("cp.async.wait_group 1;\n")
#define CPWAIT0() asm volatile("cp.async.wait_group 0;\n")

__device__ __forceinline__ void mma16(float* d, const uint32_t* a, const uint32_t* b) {
    asm volatile(
        "mma.sync.aligned.m16n8k16.row.col.f32.f16.f16.f32 "
        "{%0,%1,%2,%3}, {%4,%5,%6,%7}, {%8,%9}, {%0,%1,%2,%3};"
        : "+f"(d[0]), "+f"(d[1]), "+f"(d[2]), "+f"(d[3])
        : "r"(a[0]), "r"(a[1]), "r"(a[2]), "r"(a[3]), "r"(b[0]), "r"(b[1]));
}
__device__ __forceinline__ void mma16h(uint32_t* d, const uint32_t* a, const uint32_t* b) {
    asm volatile(
        "mma.sync.aligned.m16n8k16.row.col.f16.f16.f16.f16 "
        "{%0,%1}, {%2,%3,%4,%5}, {%6,%7}, {%0,%1};"
        : "+r"(d[0]), "+r"(d[1])
        : "r"(a[0]), "r"(a[1]), "r"(a[2]), "r"(a[3]), "r"(b[0]), "r"(b[1]));
}
__device__ __forceinline__ uint32_t h2ex2(uint32_t x) {
    uint32_t y;
    asm("ex2.approx.f16x2 %0, %1;" : "=r"(y) : "r"(x));
    return y;
}
__device__ __forceinline__ uint32_t h2addu(uint32_t a, uint32_t b) {
    __half2 r = __hadd2(*(__half2*)&a, *(__half2*)&b);
    return *(uint32_t*)&r;
}

// ---------------- prep (fused): z<5 weight transpose, z==5 x convert -------
__global__ void prep_all(const float* x, const float* Wq, const float* Wk,
                         const float* Wv, const float* Wg, const float* Wo) {
    __shared__ float t[32][33];
    int z = blockIdx.z;
    int tx = threadIdx.x, ty = threadIdx.y;
    if (z == 5) {
        int base = (blockIdx.y * 32 + blockIdx.x) * 256 + ty * 32 + tx;
#pragma unroll 4
        for (int i = base; i < MM * EE / 2; i += 32 * 32 * 256) {
            float2 v = ((const float2*)x)[i];
            ((__half2*)g_Xh)[i] = __floats2half2_rn(v.x, v.y);
        }
        return;
    }
    const float* W = z==0?Wq : z==1?Wk : z==2?Wv : z==3?Wg : Wo;
    __half* D = g_WT[z];
    int n0 = blockIdx.x*32, k0 = blockIdx.y*32;
#pragma unroll
    for (int j = 0; j < 4; ++j)
        t[ty + j*8][tx] = W[(size_t)(k0 + ty + j*8)*GN + n0 + tx];
    __syncthreads();
#pragma unroll
    for (int j = 0; j < 4; ++j)
        D[(size_t)(n0 + ty + j*8)*GK + k0 + tx] = __float2half_rn(t[tx][ty + j*8]);
}

// ---------------- GEMM core: 256 thr, 8 warps (4x2), warp tile 32x64 -------
// Optional A2: A-tile = A + A2 summed at load time (LDG+hadd2+STS; no extra smem).
#define AST 72
#define TILE_H (128*AST)
#define GEMM_SMEM (4*TILE_H*2)        // As[2] + Bs[2]

__device__ __forceinline__ void gemm_core(
    const __half* __restrict__ A, const __half* __restrict__ A2,
    const __half* __restrict__ Bt,
    const float* __restrict__ bias, float* __restrict__ fC,
    __half* __restrict__ hC, int mode)
{
    extern __shared__ char smp[];
    __half* As = (__half*)smp;
    __half* Bs = (__half*)smp + 2*TILE_H;

    const int tid = threadIdx.x, lane = tid & 31, wid = tid >> 5;
    const int wm = wid >> 1, wn = wid & 1, g = lane >> 2, c = lane & 3;
    const int row0 = blockIdx.y*128, col0 = blockIdx.x*128;

    float acc[2][8][4];
#pragma unroll
    for (int mi = 0; mi < 2; ++mi)
#pragma unroll
        for (int ni = 0; ni < 8; ++ni) {
            acc[mi][ni][0]=0.f; acc[mi][ni][1]=0.f; acc[mi][ni][2]=0.f; acc[mi][ni][3]=0.f;
        }

    auto load_chunk = [&](int buf, int k0) {
#pragma unroll
        for (int u = 0; u < 4; ++u) {
            int idx = tid + u*256, r = idx >> 3, ko = (idx & 7)*8;
            if (!A2) {
                CP16(smem_u32(&As[buf*TILE_H + r*AST + ko]), &A[(size_t)(row0+r)*GK + k0 + ko]);
            } else {
                uint4 va = *(const uint4*)&A[(size_t)(row0+r)*GK + k0 + ko];
                uint4 vb = *(const uint4*)&A2[(size_t)(row0+r)*GK + k0 + ko];
                uint4 vc;
                vc.x = h2addu(va.x, vb.x); vc.y = h2addu(va.y, vb.y);
                vc.z = h2addu(va.z, vb.z); vc.w = h2addu(va.w, vb.w);
                *(uint4*)&As[buf*TILE_H + r*AST + ko] = vc;
            }
            CP16(smem_u32(&Bs[buf*TILE_H + r*AST + ko]), &Bt[(size_t)(col0+r)*GK + k0 + ko]);
        }
        CPCOMMIT();
    };

    load_chunk(0, 0);

#pragma unroll 1
    for (int it = 0; it < 16; ++it) {
        if (it < 15) {
            load_chunk((it+1) & 1, (it+1)*64);
            CPWAIT1();
        } else {
            CPWAIT0();
        }
        __syncthreads();
        const __half* Ab = &As[(it & 1)*TILE_H];
        const __half* Bb = &Bs[(it & 1)*TILE_H];
#pragma unroll
        for (int ks = 0; ks < 4; ++ks) {
            int kb = ks*16;
            uint32_t a[2][4];
#pragma unroll
            for (int mi = 0; mi < 2; ++mi) {
                int r = wm*32 + mi*16 + g;
                a[mi][0] = *(const uint32_t*)&Ab[r*AST + kb + 2*c];
                a[mi][1] = *(const uint32_t*)&Ab[(r+8)*AST + kb + 2*c];
                a[mi][2] = *(const uint32_t*)&Ab[r*AST + kb + 8 + 2*c];
                a[mi][3] = *(const uint32_t*)&Ab[(r+8)*AST + kb + 8 + 2*c];
            }
#pragma unroll
            for (int ni = 0; ni < 8; ++ni) {
                int n = wn*64 + ni*8 + g;
                uint32_t b[2];
                b[0] = *(const uint32_t*)&Bb[n*AST + kb + 2*c];
                b[1] = *(const uint32_t*)&Bb[n*AST + kb + 8 + 2*c];
                mma16(acc[0][ni], a[0], b);
                mma16(acc[1][ni], a[1], b);
            }
        }
        __syncthreads();
    }

#pragma unroll
    for (int mi = 0; mi < 2; ++mi) {
#pragma unroll
        for (int ni = 0; ni < 8; ++ni) {
            int r = row0 + wm*32 + mi*16 + g;
            int col = col0 + wn*64 + ni*8 + 2*c;
            float b0 = 0.f, b1 = 0.f;
            if (bias) { b0 = bias[col]; b1 = bias[col+1]; }
            float v0 = acc[mi][ni][0]+b0, v1 = acc[mi][ni][1]+b1;
            float v2 = acc[mi][ni][2]+b0, v3 = acc[mi][ni][3]+b1;
            if (mode == 0) {
                const float f = SCALE * LOG2E;
                v0*=f; v1*=f; v2*=f; v3*=f;
            }
            if (mode == 4) {
                *(float2*)&fC[(size_t)r*GN + col] = make_float2(v0, v1);
                *(float2*)&fC[(size_t)(r+8)*GN + col] = make_float2(v2, v3);
            } else if (mode == 3) {
                float s0 = 1.f/(1.f+__expf(-v0)), s1 = 1.f/(1.f+__expf(-v1));
                float s2 = 1.f/(1.f+__expf(-v2)), s3 = 1.f/(1.f+__expf(-v3));
                *(__half2*)&hC[(size_t)r*GN + col] = __floats2half2_rn(s0, s1);
                *(__half2*)&hC[(size_t)(r+8)*GN + col] = __floats2half2_rn(s2, s3);
            } else if (mode == 2) {
                int bi = r >> 11, tok = r & 2047, hh = col >> 6, d = col & 63;
                __half* Vb = &g_Vt[(size_t)((bi*HH + hh)*DD) * SS];
                Vb[(size_t)d*SS + tok]       = __float2half_rn(v0);
                Vb[(size_t)(d+1)*SS + tok]   = __float2half_rn(v1);
                Vb[(size_t)d*SS + tok+8]     = __float2half_rn(v2);
                Vb[(size_t)(d+1)*SS + tok+8] = __float2half_rn(v3);
            } else {
                *(__half2*)&hC[(size_t)r*GN + col] = __floats2half2_rn(v0, v1);
                *(__half2*)&hC[(size_t)(r+8)*GN + col] = __floats2half2_rn(v2, v3);
            }
        }
    }
}

__global__ __launch_bounds__(256, 2) void gemm_qkvg(
    const float* bq, const float* bk, const float* bv)
{
    int z = blockIdx.z;
    const float* bias = z==0?bq : z==1?bk : z==2?bv : nullptr;
    __half* hC = z==0?g_Qh : z==1?g_Kh : z==2?nullptr : g_Gh;
    gemm_core(g_Xh, nullptr, g_WT[z], bias, nullptr, hC, z);
}
__global__ __launch_bounds__(256, 2) void gemm_out(const float* bo, float* out)
{
    gemm_core(g_O0h, g_O1h, g_WT[4], bo, out, nullptr, 4);
}

// ---------------- Attention (R13, unchanged): f16-score flash ----------------
#define KST 72
#define Q_OFF 0
#define K_OFF (128*KST)
#define V_OFF (K_OFF + 2*64*KST)
#define MSK_OFF_B ((V_OFF + 2*64*KST)*2)
#define ATT_SMEM (MSK_OFF_B + 128)
#define HINF 0xFC00u
#define HONE2 0x3C003C00u

__global__ __launch_bounds__(128) void attn_h(const unsigned char* __restrict__ mask)
{
    extern __shared__ char smc[];
    __half* Qs = (__half*)smc + Q_OFF;
    __half* Ks = (__half*)smc + K_OFF;
    __half* Vs = (__half*)smc + V_OFF;
    unsigned char* mskb = (unsigned char*)smc + MSK_OFF_B;

    const int tid = threadIdx.x, lane = tid & 31, wid = tid >> 5;
    const int g = lane >> 2, c = lane & 3;
    const int h = blockIdx.y, z = blockIdx.z;
    const int b = z >> 1, p = z & 1;
    const int q0 = blockIdx.x*128, hoff = h*DD;
    const int kbase = p*1024;
    const float pw = p ? 1.0f : 0.5f;
    const int wrow = wid*32;
    const __half* Kg = &g_Kh[(size_t)b*SS*EE + hoff];
    const __half* Vg = &g_Vt[(size_t)(b*HH + h)*DD*SS];

    auto issue = [&](int t) {
        int buf = t & 1, k0g = kbase + t*64;
#pragma unroll
        for (int u = 0; u < 4; ++u) {
            int idx = tid + u*128, r = idx >> 3, ko = (idx & 7)*8;
            CP16(smem_u32(&Ks[buf*64*KST + r*KST + ko]), &Kg[(size_t)(k0g + r)*EE + ko]);
            CP16(smem_u32(&Vs[buf*64*KST + r*KST + ko]), &Vg[(size_t)r*SS + k0g + ko]);
        }
        if (tid < 4)
            CP16(smem_u32(&mskb[(t & 1)*64 + tid*16]), &mask[(size_t)b*SS + k0g + tid*16]);
        CPCOMMIT();
    };

#pragma unroll
    for (int u = 0; u < 8; ++u) {
        int idx = tid + u*128, r = idx >> 3, ko = (idx & 7)*8;
        CP16(smem_u32(&Qs[r*KST + ko]), &g_Qh[(size_t)(b*SS + q0 + r)*EE + hoff + ko]);
    }
    issue(0);

    float o[2][8][4];
    float lac[2][4];
#pragma unroll
    for (int mi = 0; mi < 2; ++mi) {
        lac[mi][0]=0.f; lac[mi][1]=0.f; lac[mi][2]=0.f; lac[mi][3]=0.f;
#pragma unroll
        for (int ni = 0; ni < 8; ++ni) {
            o[mi][ni][0]=0.f; o[mi][ni][1]=0.f; o[mi][ni][2]=0.f; o[mi][ni][3]=0.f;
        }
    }
    const uint32_t ones2[2] = {HONE2, HONE2};

#pragma unroll 1
    for (int t = 0; t < 16; ++t) {
        if (t < 15) { issue(t + 1); CPWAIT1(); } else { CPWAIT0(); }
        __syncthreads();
        const __half* Kb = &Ks[(t & 1)*64*KST];
        const __half* Vb = &Vs[(t & 1)*64*KST];
        const unsigned char* mb = &mskb[(t & 1)*64];

        uint32_t s[2][8][2];
#pragma unroll
        for (int mi = 0; mi < 2; ++mi)
#pragma unroll
            for (int ni = 0; ni < 8; ++ni) { s[mi][ni][0]=0u; s[mi][ni][1]=0u; }
#pragma unroll
        for (int ks = 0; ks < 4; ++ks) {
            int kb = ks*16;
            uint32_t a[2][4];
#pragma unroll
            for (int mi = 0; mi < 2; ++mi) {
                int r = wrow + mi*16 + g;
                a[mi][0] = *(const uint32_t*)&Qs[r*KST + kb + 2*c];
                a[mi][1] = *(const uint32_t*)&Qs[(r+8)*KST + kb + 2*c];
                a[mi][2] = *(const uint32_t*)&Qs[r*KST + kb + 8 + 2*c];
                a[mi][3] = *(const uint32_t*)&Qs[(r+8)*KST + kb + 8 + 2*c];
            }
#pragma unroll
            for (int ni = 0; ni < 8; ++ni) {
                int n = ni*8 + g;
                uint32_t bf[2];
                bf[0] = *(const uint32_t*)&Kb[n*KST + kb + 2*c];
                bf[1] = *(const uint32_t*)&Kb[n*KST + kb + 8 + 2*c];
                mma16h(s[0][ni], a[0], bf);
                mma16h(s[1][ni], a[1], bf);
            }
        }

        uint32_t mh[8];
#pragma unroll
        for (int ni = 0; ni < 8; ++ni)
            mh[ni] = (mb[ni*8 + 2*c] ? HINF : 0u) | (mb[ni*8 + 2*c + 1] ? (HINF << 16) : 0u);
#pragma unroll
        for (int mi = 0; mi < 2; ++mi)
#pragma unroll
            for (int ni = 0; ni < 8; ++ni) {
                s[mi][ni][0] = h2ex2(h2addu(s[mi][ni][0], mh[ni]));
                s[mi][ni][1] = h2ex2(h2addu(s[mi][ni][1], mh[ni]));
            }

#pragma unroll
        for (int kc = 0; kc < 4; ++kc) {
            uint32_t ap[2][4];
#pragma unroll
            for (int mi = 0; mi < 2; ++mi) {
                ap[mi][0] = s[mi][2*kc][0];
                ap[mi][1] = s[mi][2*kc][1];
                ap[mi][2] = s[mi][2*kc+1][0];
                ap[mi][3] = s[mi][2*kc+1][1];
            }
#pragma unroll
            for (int ni = 0; ni < 8; ++ni) {
                int n = ni*8 + g;
                uint32_t bf[2];
                bf[0] = *(const uint32_t*)&Vb[n*KST + kc*16 + 2*c];
                bf[1] = *(const uint32_t*)&Vb[n*KST + kc*16 + 8 + 2*c];
                mma16(o[0][ni], ap[0], bf);
                mma16(o[1][ni], ap[1], bf);
            }
            mma16(lac[0], ap[0], ones2);
            mma16(lac[1], ap[1], ones2);
        }
        __syncthreads();
    }

    __half* Op = p ? g_O1h : g_O0h;
#pragma unroll
    for (int mi = 0; mi < 2; ++mi) {
        const int r0 = q0 + wrow + mi*16 + g, r1 = r0 + 8;
        const float inv0 = pw / lac[mi][0], inv1 = pw / lac[mi][2];
#pragma unroll
        for (int ni = 0; ni < 8; ++ni) {
            int col = hoff + ni*8 + 2*c;
            size_t i0 = (size_t)(b*SS + r0)*EE + col;
            size_t i1 = (size_t)(b*SS + r1)*EE + col;
            float v0 = o[mi][ni][0]*inv0, v1 = o[mi][ni][1]*inv0;
            float v2 = o[mi][ni][2]*inv1, v3 = o[mi][ni][3]*inv1;
            if (r0 >= 1) {
                __half2 gh = *(const __half2*)&g_Gh[i0];
                v0 *= __half2float(gh.x);
                v1 *= __half2float(gh.y);
            }
            __half2 gw = *(const __half2*)&g_Gh[i1];
            v2 *= __half2float(gw.x);
            v3 *= __half2float(gw.y);
            *(__half2*)&Op[i0] = __floats2half2_rn(v0, v1);
            *(__half2*)&Op[i1] = __floats2half2_rn(v2, v3);
        }
    }
}

// ---------------- launch ----------------
extern "C" void kernel_launch(void* const* d_in, const int* in_sizes, int n_in,
                              void* d_out, int out_size)
{
    const float* x  = (const float*)d_in[0];
    const float* Wq = (const float*)d_in[1];
    const float* bq = (const float*)d_in[2];
    const float* Wk = (const float*)d_in[3];
    const float* bk = (const float*)d_in[4];
    const float* Wv = (const float*)d_in[5];
    const float* bv = (const float*)d_in[6];
    const float* Wo = (const float*)d_in[7];
    const float* bo = (const float*)d_in[8];
    const float* Wg = (const float*)d_in[9];
    const unsigned char* mask = (const unsigned char*)d_in[10];
    float* out = (float*)d_out;

    static int attr_set = 0;
    if (!attr_set) {
        cudaFuncSetAttribute(gemm_qkvg, cudaFuncAttributeMaxDynamicSharedMemorySize, GEMM_SMEM);
        cudaFuncSetAttribute(gemm_out,  cudaFuncAttributeMaxDynamicSharedMemorySize, GEMM_SMEM);
        cudaFuncSetAttribute(attn_h,    cudaFuncAttributeMaxDynamicSharedMemorySize, ATT_SMEM);
        attr_set = 1;
    }

    prep_all<<<dim3(32, 32, 6), dim3(32, 8)>>>(x, Wq, Wk, Wv, Wg, Wo);
    gemm_qkvg<<<dim3(8, 32, 4), 256, GEMM_SMEM>>>(bq, bk, bv);
    attn_h<<<dim3(SS/128, HH, BB*2), 128, ATT_SMEM>>>(mask);
    gemm_out<<<dim3(8, 32), 256, GEMM_SMEM>>>(bo, out);
}